// round 15
// baseline (speedup 1.0000x reference)
#include <cuda_runtime.h>
#include <cuda_bf16.h>
#include <cuda_fp16.h>
#include <cstdint>

#define NNODES 100000
#define NEDGES 800000
#define DH 96
#define C4 (DH / 4)

#define GBM 64
#define GEMM_BLOCKS ((NNODES + GBM - 1) / GBM)   // 1563
#define GATH1_BLOCKS (NNODES / 8)                // 12500 (8 nodes per 256-thr block)
#define HIST_BLOCKS ((NEDGES + 255) / 256)       // 3125
#define WPREP_TOTAL (2 * 2 * 2 * 6 * 6 * 32)     // 9216
#define WPREP_BLOCKS ((WPREP_TOTAL + 255) / 256) // 36

// ---- scratch ----
__device__ __half g_H[NNODES * DH];     // Hs table (fp16): dis[r] * (A'@W)[r]
__device__ __half g_AGG[NNODES * DH];   // layer-1 activation (fp16): relu(agg+b1)
__device__ float  g_dis[NNODES];
// meta: [0,N)=cnt/deg, [N]=scan ticket, [N+1 .. N+1+GEMM_BLOCKS)=pipe done flags
__device__ int    g_meta[NNODES + 2048];
__device__ int    g_epos[NEDGES];       // per-edge slot within its dst bucket
__device__ int    g_off[NNODES];        // per-chunk exclusive prefix
__device__ int    g_bsum[256];          // chunk sums -> exclusive after scan finalize
__device__ int    g_csr[NEDGES];
// B fragments: [layer][var(hi/lo)][np(2)][kt(6)][nt(6)][lane(32)] -> uint2
__device__ uint2  g_Bfrag[2 * 2 * 2 * 6 * 6 * 32];

// ============================ helpers ============================

__device__ __forceinline__ uint32_t cvt_bf16x2(float lo, float hi) {
    uint32_t r;
    asm("cvt.rn.satfinite.bf16x2.f32 %0, %1, %2;" : "=r"(r) : "f"(hi), "f"(lo));
    return r;
}

__device__ __forceinline__ void mma_bf16(float* c, const uint32_t* a,
                                         uint32_t b0, uint32_t b1) {
    asm volatile(
        "mma.sync.aligned.m16n8k16.row.col.f32.bf16.bf16.f32 "
        "{%0,%1,%2,%3}, {%4,%5,%6,%7}, {%8,%9}, {%0,%1,%2,%3};"
        : "+f"(c[0]), "+f"(c[1]), "+f"(c[2]), "+f"(c[3])
        : "r"(a[0]), "r"(a[1]), "r"(a[2]), "r"(a[3]), "r"(b0), "r"(b1));
}

__device__ __forceinline__ void split_store(char* phi, char* plo, int byte_off,
                                            float x, float y, float z, float w) {
    uint32_t h01 = cvt_bf16x2(x, y);
    uint32_t h23 = cvt_bf16x2(z, w);
    float lx = x - __uint_as_float(h01 << 16);
    float ly = y - __uint_as_float(h01 & 0xFFFF0000u);
    float lz = z - __uint_as_float(h23 << 16);
    float lw = w - __uint_as_float(h23 & 0xFFFF0000u);
    *(uint2*)(phi + byte_off) = make_uint2(h01, h23);
    *(uint2*)(plo + byte_off) = make_uint2(cvt_bf16x2(lx, ly), cvt_bf16x2(lz, lw));
}

__device__ __forceinline__ int ld_acquire(const int* p) {
    int v;
    asm volatile("ld.global.acquire.gpu.b32 %0, [%1];" : "=r"(v) : "l"(p));
    return v;
}

// ============================ W fragment prep ============================

__device__ __forceinline__ void wprep_body(int idx, const float* __restrict__ W1,
                                           const float* __restrict__ W2) {
    if (idx >= WPREP_TOTAL) return;
    int lane = idx & 31;
    int t = idx >> 5;
    int nt = t % 6;  t /= 6;
    int kt = t % 6;  t /= 6;
    int np = t % 2;  t /= 2;
    int var = t % 2; t /= 2;
    int layer = t;
    const float* W = layer ? W2 : W1;

    int n  = np * 48 + nt * 8 + (lane >> 2);
    int k0 = kt * 16 + (lane & 3) * 2;
    float v[4];
#pragma unroll
    for (int i = 0; i < 4; i++) {
        int k = k0 + (i & 1) + (i >> 1) * 8;
        float w = W[k * DH + n];
        float hi = __bfloat162float(__float2bfloat16(w));
        v[i] = var ? (w - hi) : hi;
    }
    g_Bfrag[idx] = make_uint2(cvt_bf16x2(v[0], v[1]), cvt_bf16x2(v[2], v[3]));
}

// hist (records per-edge slot in g_epos) || wprep
__global__ void hist_wprep_kernel(const int* __restrict__ ei,
                                  const float* __restrict__ W1,
                                  const float* __restrict__ W2) {
    if (blockIdx.x < WPREP_BLOCKS) {
        wprep_body(blockIdx.x * blockDim.x + threadIdx.x, W1, W2);
    } else {
        int e = (blockIdx.x - WPREP_BLOCKS) * blockDim.x + threadIdx.x;
        if (e < NEDGES) {
            int d = ei[NEDGES + e];
            g_epos[e] = atomicAdd(&g_meta[d], 1);   // count AND slot
        }
    }
}

// ============================ combined scan (scan1 + last-block scan2) ========

#define SCHUNK 512
#define NSBLK ((NNODES + SCHUNK - 1) / SCHUNK)   // 196

__global__ void scan_kernel() {
    __shared__ int wsum[16];
    __shared__ int s_last;
    const int t = threadIdx.x;
    const int lane = t & 31, warp = t >> 5;
    const int i = blockIdx.x * SCHUNK + t;
    const int v = (i < NNODES) ? g_meta[i] : 0;
    int x = v;
#pragma unroll
    for (int o = 1; o < 32; o <<= 1) {
        int y = __shfl_up_sync(0xFFFFFFFF, x, o);
        if (lane >= o) x += y;
    }
    if (lane == 31) wsum[warp] = x;
    __syncthreads();
    if (warp == 0) {
        int s = (lane < 16) ? wsum[lane] : 0;
#pragma unroll
        for (int o = 1; o < 16; o <<= 1) {
            int y = __shfl_up_sync(0xFFFFFFFF, s, o);
            if (lane >= o) s += y;
        }
        if (lane < 16) wsum[lane] = s;
    }
    __syncthreads();
    const int base = (warp > 0) ? wsum[warp - 1] : 0;
    if (i < NNODES) {
        g_off[i] = base + x - v;
        g_dis[i] = rsqrtf((float)v + 1.0f);
    }
    if (t == SCHUNK - 1) g_bsum[blockIdx.x] = base + x;

    // release our bsum, take a ticket; the LAST block finalizes (scan2)
    __threadfence();
    if (t == 0) {
        int ticket = atomicAdd(&g_meta[NNODES], 1);
        s_last = (ticket == NSBLK - 1) ? 1 : 0;
    }
    __syncthreads();
    if (s_last && warp == 0) {
        const int b7 = lane * 7;
        int vv[7], inc[7];
        int tot = 0;
#pragma unroll
        for (int j = 0; j < 7; j++) {
            vv[j] = (b7 + j < NSBLK) ? __ldcg(&g_bsum[b7 + j]) : 0;
            tot += vv[j];
            inc[j] = tot;
        }
        int xx = tot;
#pragma unroll
        for (int o = 1; o < 32; o <<= 1) {
            int y = __shfl_up_sync(0xFFFFFFFF, xx, o);
            if (lane >= o) xx += y;
        }
        const int excl = xx - tot;
#pragma unroll
        for (int j = 0; j < 7; j++)
            if (b7 + j < NSBLK) g_bsum[b7 + j] = excl + inc[j] - vv[j];
    }
}

// ============================ GEMM pieces (HMMA) ============================

#define APITCH 104
#define AROW_BYTES (APITCH * 2)
#define SM_AHI 0
#define SM_ALO (GBM * AROW_BYTES)
#define GEMM_SMEM (2 * GBM * AROW_BYTES)   // 26624

__device__ __forceinline__ void gemm_compute(char* smem, int row0,
                                             const uint2* __restrict__ Bfrag,
                                             __half* __restrict__ H) {
    const int tid = threadIdx.x;
    const int lane = tid & 31;
    const int wid = tid >> 5;
    const int wm = wid & 1;
    const int wn = wid >> 1;

    float acc[2][3][4];
#pragma unroll
    for (int m = 0; m < 2; m++)
#pragma unroll
        for (int nt = 0; nt < 3; nt++)
#pragma unroll
            for (int i = 0; i < 4; i++) acc[m][nt][i] = 0.0f;

    const int fr = (lane >> 2);
    const int fk = (lane & 3) * 2;

#pragma unroll
    for (int kt = 0; kt < 6; kt++) {
        uint32_t ahi[2][4], alo[2][4];
#pragma unroll
        for (int m = 0; m < 2; m++) {
            const int r = wm * 32 + m * 16 + fr;
            const int kb = (kt * 16 + fk) * 2;
            const char* ph = smem + SM_AHI + r * AROW_BYTES + kb;
            const char* pl = smem + SM_ALO + r * AROW_BYTES + kb;
            ahi[m][0] = *(const uint32_t*)ph;
            ahi[m][1] = *(const uint32_t*)(ph + 8 * AROW_BYTES);
            ahi[m][2] = *(const uint32_t*)(ph + 16);
            ahi[m][3] = *(const uint32_t*)(ph + 8 * AROW_BYTES + 16);
            alo[m][0] = *(const uint32_t*)pl;
            alo[m][1] = *(const uint32_t*)(pl + 8 * AROW_BYTES);
            alo[m][2] = *(const uint32_t*)(pl + 16);
            alo[m][3] = *(const uint32_t*)(pl + 8 * AROW_BYTES + 16);
        }
#pragma unroll
        for (int nt = 0; nt < 3; nt++) {
            const int g = wn * 3 + nt;
            const int np = g / 6, n6 = g % 6;
            const uint2 bhi = Bfrag[(((0 * 2 + np) * 6 + kt) * 6 + n6) * 32 + lane];
            const uint2 blo = Bfrag[(((1 * 2 + np) * 6 + kt) * 6 + n6) * 32 + lane];
#pragma unroll
            for (int m = 0; m < 2; m++) {
                mma_bf16(acc[m][nt], ahi[m], bhi.x, bhi.y);
                mma_bf16(acc[m][nt], ahi[m], blo.x, blo.y);
                mma_bf16(acc[m][nt], alo[m], bhi.x, bhi.y);
            }
        }
    }

#pragma unroll
    for (int m = 0; m < 2; m++) {
        const int r = row0 + wm * 32 + m * 16 + fr;
        const float d0 = (r < NNODES) ? g_dis[r] : 0.0f;
        const float d1 = (r + 8 < NNODES) ? g_dis[r + 8] : 0.0f;
#pragma unroll
        for (int nt = 0; nt < 3; nt++) {
            const int col = (wn * 3 + nt) * 8 + fk;
            if (r < NNODES)
                *(__half2*)(H + (size_t)r * DH + col) =
                    __floats2half2_rn(acc[m][nt][0] * d0, acc[m][nt][1] * d0);
            if (r + 8 < NNODES)
                *(__half2*)(H + (size_t)(r + 8) * DH + col) =
                    __floats2half2_rn(acc[m][nt][2] * d1, acc[m][nt][3] * d1);
        }
    }
}

__device__ __forceinline__ void gemm_f32_body(char* smem, int bid,
                                              const float* __restrict__ A,
                                              const uint2* __restrict__ Bfrag,
                                              __half* __restrict__ H) {
    const int tid = threadIdx.x;
    const int row0 = bid * GBM;
    {
        const int r = tid >> 2;
        const int cb = (tid & 3) * 24;
        const int grow = row0 + r;
        char* phi = smem + SM_AHI + r * AROW_BYTES;
        char* plo = smem + SM_ALO + r * AROW_BYTES;
#pragma unroll
        for (int q = 0; q < 6; q++) {
            const int k0 = cb + q * 4;
            float4 v = (grow < NNODES)
                ? *(const float4*)(A + (size_t)grow * DH + k0)
                : make_float4(0.f, 0.f, 0.f, 0.f);
            split_store(phi, plo, k0 * 2, v.x, v.y, v.z, v.w);
        }
    }
    __syncthreads();
    gemm_compute(smem, row0, Bfrag, H);
}

// ============================ fill body ============================

__device__ __forceinline__ void fill_body(int e, const int* __restrict__ ei) {
    if (e >= NEDGES) return;
    int s = ei[e];
    int d = ei[NEDGES + e];
    int pos = g_off[d] + g_bsum[d >> 9] + g_epos[e];
    g_csr[pos] = s;
}

// ============================ gather body ============================
// One warp per node, fp16 H table, fp32 accumulation.
// r = relu(dis[d] * (Hs[d] + sum Hs[s]) + bias)

__device__ __forceinline__ void gather_node(int node, int lid,
                                            const __half* __restrict__ Hin,
                                            const float* __restrict__ bias,
                                            __half* __restrict__ out16,
                                            float* __restrict__ out32) {
    const bool active = lid < C4;
    float4 acc = make_float4(0.f, 0.f, 0.f, 0.f);
    if (active) {
        uint2 u = __ldg((const uint2*)(Hin + (size_t)node * DH) + lid);
        float2 f0 = __half22float2(*reinterpret_cast<__half2*>(&u.x));
        float2 f1 = __half22float2(*reinterpret_cast<__half2*>(&u.y));
        acc = make_float4(f0.x, f0.y, f1.x, f1.y);
    }
    int start = g_off[node] + g_bsum[node >> 9];
    int deg   = g_meta[node];
#pragma unroll 4
    for (int i = 0; i < deg; i++) {
        int s = __ldg(&g_csr[start + i]);
        if (active) {
            uint2 u = __ldg((const uint2*)(Hin + (size_t)s * DH) + lid);
            float2 f0 = __half22float2(*reinterpret_cast<__half2*>(&u.x));
            float2 f1 = __half22float2(*reinterpret_cast<__half2*>(&u.y));
            acc.x += f0.x; acc.y += f0.y; acc.z += f1.x; acc.w += f1.y;
        }
    }
    if (active) {
        float dd = g_dis[node];
        float4 b = __ldg((const float4*)bias + lid);
        acc.x = fmaxf(acc.x * dd + b.x, 0.0f);
        acc.y = fmaxf(acc.y * dd + b.y, 0.0f);
        acc.z = fmaxf(acc.z * dd + b.z, 0.0f);
        acc.w = fmaxf(acc.w * dd + b.w, 0.0f);
        if (out16) {
            uint2 u;
            *reinterpret_cast<__half2*>(&u.x) = __floats2half2_rn(acc.x, acc.y);
            *reinterpret_cast<__half2*>(&u.y) = __floats2half2_rn(acc.z, acc.w);
            ((uint2*)(out16 + (size_t)node * DH))[lid] = u;
        } else {
            ((float4*)(out32 + (size_t)node * DH))[lid] = acc;
        }
    }
}

// ============================ fused kernels ============================

// blocks [0, GEMM_BLOCKS): layer-1 GEMM; [GEMM_BLOCKS, +HIST_BLOCKS): CSR fill.
// Independent work items, both gated on scan completion (kernel boundary).
__global__ void __launch_bounds__(256)
gemm1_fill_kernel(const float* __restrict__ x, const uint2* __restrict__ Bfrag,
                  __half* __restrict__ H, const int* __restrict__ ei) {
    extern __shared__ char smem[];
    if (blockIdx.x < GEMM_BLOCKS) {
        gemm_f32_body(smem, blockIdx.x, x, Bfrag, H);
    } else {
        fill_body((blockIdx.x - GEMM_BLOCKS) * 256 + threadIdx.x, ei);
    }
}

// Producer/consumer pipe: gather1 -> AGG(fp16) -> gemm2 -> H.
// blocks [0, GATH1_BLOCKS): produce AGG rows for nodes [b*8, b*8+8),
//   then release g_done[b>>3] (threadfence + atomicAdd).
// blocks [GATH1_BLOCKS, +GEMM_BLOCKS): consumer tile b waits (acquire) for its
//   8 producer blocks, then stages AGG rows [64b, 64b+64) and runs the MMA.
__global__ void __launch_bounds__(256)
gather1_gemm2_kernel(const __half* __restrict__ Hin, const float* __restrict__ b1,
                     const uint2* __restrict__ Bfrag2,
                     __half* __restrict__ AGG, __half* __restrict__ Hout) {
    extern __shared__ char smem[];
    int* done = &g_meta[NNODES + 1];

    if (blockIdx.x < GATH1_BLOCKS) {
        const int wid = threadIdx.x >> 5;
        const int lid = threadIdx.x & 31;
        const int node = blockIdx.x * 8 + wid;
        if (node < NNODES)
            gather_node(node, lid, Hin, b1, AGG, nullptr);
        __syncthreads();
        __threadfence();                       // release AGG writes
        if (threadIdx.x == 0)
            atomicAdd(&done[blockIdx.x >> 3], 1);
    } else {
        const int b = blockIdx.x - GATH1_BLOCKS;
        const int row0 = b * GBM;
        const int expected = (min(GBM, NNODES - row0) + 7) / 8;
        if (threadIdx.x == 0) {
            while (ld_acquire(&done[b]) < expected) __nanosleep(200);
        }
        __syncthreads();

        // stage AGG (fp16) -> bf16 hi/lo smem tiles (L2 loads; producers on
        // other SMs wrote via L2; L1 has no stale lines for these addrs)
        {
            const int tid = threadIdx.x;
            const int r = tid >> 2;
            const int cb = (tid & 3) * 24;
            const int grow = row0 + r;
            char* phi = smem + SM_AHI + r * AROW_BYTES;
            char* plo = smem + SM_ALO + r * AROW_BYTES;
#pragma unroll
            for (int q = 0; q < 6; q++) {
                const int k0 = cb + q * 4;
                float4 v = make_float4(0.f, 0.f, 0.f, 0.f);
                if (grow < NNODES) {
                    uint2 u = __ldcg((const uint2*)(AGG + (size_t)grow * DH + k0));
                    float2 f0 = __half22float2(*reinterpret_cast<__half2*>(&u.x));
                    float2 f1 = __half22float2(*reinterpret_cast<__half2*>(&u.y));
                    v = make_float4(f0.x, f0.y, f1.x, f1.y);
                }
                split_store(phi, plo, k0 * 2, v.x, v.y, v.z, v.w);
            }
        }
        __syncthreads();
        gemm_compute(smem, row0, Bfrag2, Hout);
    }
}

// final gather -> fp32 out
__global__ void __launch_bounds__(256)
gather2_kernel(const __half* __restrict__ Hin, const float* __restrict__ b2,
               float* __restrict__ out) {
    int node = (blockIdx.x * blockDim.x + threadIdx.x) >> 5;
    int lid = threadIdx.x & 31;
    if (node >= NNODES) return;
    gather_node(node, lid, Hin, b2, nullptr, out);
}

// ============================ launch ============================

extern "C" void kernel_launch(void* const* d_in, const int* in_sizes, int n_in,
                              void* d_out, int out_size) {
    const float* x  = (const float*)d_in[0];
    const int*   ei = (const int*)d_in[1];
    const float* W1 = (const float*)d_in[2];
    const float* b1 = (const float*)d_in[3];
    const float* W2 = (const float*)d_in[4];
    const float* b2 = (const float*)d_in[5];
    float* out = (float*)d_out;

    void *pH_v, *pAGG_v, *pBf_v, *pMeta_v;
    cudaGetSymbolAddress(&pH_v, g_H);
    cudaGetSymbolAddress(&pAGG_v, g_AGG);
    cudaGetSymbolAddress(&pBf_v, g_Bfrag);
    cudaGetSymbolAddress(&pMeta_v, g_meta);
    __half* pH   = (__half*)pH_v;
    __half* pAGG = (__half*)pAGG_v;
    const uint2* pBf = (const uint2*)pBf_v;

    cudaFuncSetAttribute(gemm1_fill_kernel,
                         cudaFuncAttributeMaxDynamicSharedMemorySize, GEMM_SMEM);
    cudaFuncSetAttribute(gather1_gemm2_kernel,
                         cudaFuncAttributeMaxDynamicSharedMemorySize, GEMM_SMEM);

    const int T = 256;
    int nBlkGath2 = (NNODES * 32 + T - 1) / T;

    // 1. zero meta (cnt + scan ticket + pipe flags)
    cudaMemsetAsync(pMeta_v, 0, (NNODES + 2048) * sizeof(int));
    // 2. hist (+ per-edge slot) || wprep
    hist_wprep_kernel<<<WPREP_BLOCKS + HIST_BLOCKS, T>>>(ei, W1, W2);
    // 3. combined scan (per-chunk + last-block finalize) + dis
    scan_kernel<<<NSBLK, SCHUNK>>>();
    // 4. layer-1 GEMM || CSR fill (independent)
    gemm1_fill_kernel<<<GEMM_BLOCKS + HIST_BLOCKS, T, GEMM_SMEM>>>(x, pBf, pH, ei);
    // 5. gather1 -> gemm2 pipe (producers first; tile-grain acquire/release)
    gather1_gemm2_kernel<<<GATH1_BLOCKS + GEMM_BLOCKS, T, GEMM_SMEM>>>(
        pH, b1, pBf + 4608, pAGG, pH);
    // 6. final gather -> out
    gather2_kernel<<<nBlkGath2, T>>>(pH, b2, out);
}

// round 16
// speedup vs baseline: 1.3442x; 1.3442x over previous
#include <cuda_runtime.h>
#include <cuda_bf16.h>
#include <cuda_fp16.h>
#include <cstdint>

#define NNODES 100000
#define NEDGES 800000
#define DH 96
#define C4 (DH / 4)

#define GBM 64
#define GEMM_BLOCKS ((NNODES + GBM - 1) / GBM)   // 1563
#define HIST_BLOCKS ((NEDGES + 255) / 256)       // 3125
#define WPREP_TOTAL (2 * 2 * 2 * 6 * 6 * 32)     // 9216
#define WPREP_BLOCKS ((WPREP_TOTAL + 255) / 256) // 36

// ---- scratch ----
__device__ __half g_H[NNODES * DH];     // Hs table (fp16): dis[r] * (A'@W)[r]
__device__ __half g_AGG[NNODES * DH];   // layer-1 activation (fp16): relu(agg+b1)
__device__ float  g_dis[NNODES];
__device__ int    g_meta[NNODES + 1];   // [0,N)=cnt/deg, [N]=scan ticket
__device__ int    g_epos[NEDGES];       // per-edge slot within its dst bucket
__device__ int    g_off[NNODES];        // per-chunk exclusive prefix
__device__ int    g_bsum[256];          // chunk sums -> exclusive after finalize
__device__ int    g_csr[NEDGES];
// B fragments: [layer][var(hi/lo)][np(2)][kt(6)][nt(6)][lane(32)] -> uint2
__device__ uint2  g_Bfrag[2 * 2 * 2 * 6 * 6 * 32];

#define PDL_SYNC()    cudaGridDependencySynchronize()
#define PDL_TRIGGER() cudaTriggerProgrammaticLaunchCompletion()

// ============================ helpers ============================

__device__ __forceinline__ uint32_t cvt_bf16x2(float lo, float hi) {
    uint32_t r;
    asm("cvt.rn.satfinite.bf16x2.f32 %0, %1, %2;" : "=r"(r) : "f"(hi), "f"(lo));
    return r;
}

__device__ __forceinline__ void mma_bf16(float* c, const uint32_t* a,
                                         uint32_t b0, uint32_t b1) {
    asm volatile(
        "mma.sync.aligned.m16n8k16.row.col.f32.bf16.bf16.f32 "
        "{%0,%1,%2,%3}, {%4,%5,%6,%7}, {%8,%9}, {%0,%1,%2,%3};"
        : "+f"(c[0]), "+f"(c[1]), "+f"(c[2]), "+f"(c[3])
        : "r"(a[0]), "r"(a[1]), "r"(a[2]), "r"(a[3]), "r"(b0), "r"(b1));
}

__device__ __forceinline__ void split_store(char* phi, char* plo, int byte_off,
                                            float x, float y, float z, float w) {
    uint32_t h01 = cvt_bf16x2(x, y);
    uint32_t h23 = cvt_bf16x2(z, w);
    float lx = x - __uint_as_float(h01 << 16);
    float ly = y - __uint_as_float(h01 & 0xFFFF0000u);
    float lz = z - __uint_as_float(h23 << 16);
    float lw = w - __uint_as_float(h23 & 0xFFFF0000u);
    *(uint2*)(phi + byte_off) = make_uint2(h01, h23);
    *(uint2*)(plo + byte_off) = make_uint2(cvt_bf16x2(lx, ly), cvt_bf16x2(lz, lw));
}

// ============================ pre-pass kernels ============================

__global__ void zero_kernel() {
    int i = blockIdx.x * blockDim.x + threadIdx.x;
    if (i < NNODES + 1) g_meta[i] = 0;
}

__device__ __forceinline__ void wprep_body(int idx, const float* __restrict__ W1,
                                           const float* __restrict__ W2) {
    if (idx >= WPREP_TOTAL) return;
    int lane = idx & 31;
    int t = idx >> 5;
    int nt = t % 6;  t /= 6;
    int kt = t % 6;  t /= 6;
    int np = t % 2;  t /= 2;
    int var = t % 2; t /= 2;
    int layer = t;
    const float* W = layer ? W2 : W1;

    int n  = np * 48 + nt * 8 + (lane >> 2);
    int k0 = kt * 16 + (lane & 3) * 2;
    float v[4];
#pragma unroll
    for (int i = 0; i < 4; i++) {
        int k = k0 + (i & 1) + (i >> 1) * 8;
        float w = W[k * DH + n];
        float hi = __bfloat162float(__float2bfloat16(w));
        v[i] = var ? (w - hi) : hi;
    }
    g_Bfrag[idx] = make_uint2(cvt_bf16x2(v[0], v[1]), cvt_bf16x2(v[2], v[3]));
}

// hist (records per-edge slot in g_epos) || wprep
__global__ void hist_wprep_kernel(const int* __restrict__ ei,
                                  const float* __restrict__ W1,
                                  const float* __restrict__ W2) {
    if (blockIdx.x < WPREP_BLOCKS) {
        wprep_body(blockIdx.x * blockDim.x + threadIdx.x, W1, W2);   // inputs only
    } else {
        int e = (blockIdx.x - WPREP_BLOCKS) * blockDim.x + threadIdx.x;
        int d = (e < NEDGES) ? ei[NEDGES + e] : 0;   // input load pre-sync
        PDL_SYNC();                                   // g_meta zeroed
        if (e < NEDGES)
            g_epos[e] = atomicAdd(&g_meta[d], 1);     // count AND slot
    }
    PDL_TRIGGER();
}

// ============================ combined scan ============================

#define SCHUNK 512
#define NSBLK ((NNODES + SCHUNK - 1) / SCHUNK)   // 196

__global__ void scan_kernel() {
    __shared__ int wsum[16];
    __shared__ int s_last;
    PDL_SYNC();
    const int t = threadIdx.x;
    const int lane = t & 31, warp = t >> 5;
    const int i = blockIdx.x * SCHUNK + t;
    const int v = (i < NNODES) ? g_meta[i] : 0;
    int x = v;
#pragma unroll
    for (int o = 1; o < 32; o <<= 1) {
        int y = __shfl_up_sync(0xFFFFFFFF, x, o);
        if (lane >= o) x += y;
    }
    if (lane == 31) wsum[warp] = x;
    __syncthreads();
    if (warp == 0) {
        int s = (lane < 16) ? wsum[lane] : 0;
#pragma unroll
        for (int o = 1; o < 16; o <<= 1) {
            int y = __shfl_up_sync(0xFFFFFFFF, s, o);
            if (lane >= o) s += y;
        }
        if (lane < 16) wsum[lane] = s;
    }
    __syncthreads();
    const int base = (warp > 0) ? wsum[warp - 1] : 0;
    if (i < NNODES) {
        g_off[i] = base + x - v;
        g_dis[i] = rsqrtf((float)v + 1.0f);
    }
    if (t == SCHUNK - 1) g_bsum[blockIdx.x] = base + x;

    // release bsum, take a ticket; the LAST block finalizes (old scan2)
    __threadfence();
    if (t == 0) {
        int ticket = atomicAdd(&g_meta[NNODES], 1);
        s_last = (ticket == NSBLK - 1) ? 1 : 0;
    }
    __syncthreads();
    if (s_last && warp == 0) {
        const int b7 = lane * 7;
        int vv[7], inc[7];
        int tot = 0;
#pragma unroll
        for (int j = 0; j < 7; j++) {
            vv[j] = (b7 + j < NSBLK) ? __ldcg(&g_bsum[b7 + j]) : 0;
            tot += vv[j];
            inc[j] = tot;
        }
        int xx = tot;
#pragma unroll
        for (int o = 1; o < 32; o <<= 1) {
            int y = __shfl_up_sync(0xFFFFFFFF, xx, o);
            if (lane >= o) xx += y;
        }
        const int excl = xx - tot;
#pragma unroll
        for (int j = 0; j < 7; j++)
            if (b7 + j < NSBLK) g_bsum[b7 + j] = excl + inc[j] - vv[j];
    }
    PDL_TRIGGER();
}

// ============================ fill ============================

__global__ void fill_kernel(const int* __restrict__ ei) {
    int e = blockIdx.x * blockDim.x + threadIdx.x;
    int s = 0, d = 0;
    if (e < NEDGES) { s = ei[e]; d = ei[NEDGES + e]; }   // input loads pre-sync
    PDL_SYNC();
    if (e < NEDGES) {
        int pos = g_off[d] + g_bsum[d >> 9] + g_epos[e];
        g_csr[pos] = s;
    }
    PDL_TRIGGER();
}

// ============================ GEMM (HMMA) ============================

#define APITCH 104
#define AROW_BYTES (APITCH * 2)
#define SM_AHI 0
#define SM_ALO (GBM * AROW_BYTES)
#define GEMM_SMEM (2 * GBM * AROW_BYTES)   // 26624

__device__ __forceinline__ void gemm_compute(char* smem, int row0,
                                             const uint2* __restrict__ Bfrag,
                                             __half* __restrict__ H) {
    const int tid = threadIdx.x;
    const int lane = tid & 31;
    const int wid = tid >> 5;
    const int wm = wid & 1;
    const int wn = wid >> 1;

    float acc[2][3][4];
#pragma unroll
    for (int m = 0; m < 2; m++)
#pragma unroll
        for (int nt = 0; nt < 3; nt++)
#pragma unroll
            for (int i = 0; i < 4; i++) acc[m][nt][i] = 0.0f;

    const int fr = (lane >> 2);
    const int fk = (lane & 3) * 2;

#pragma unroll
    for (int kt = 0; kt < 6; kt++) {
        uint32_t ahi[2][4], alo[2][4];
#pragma unroll
        for (int m = 0; m < 2; m++) {
            const int r = wm * 32 + m * 16 + fr;
            const int kb = (kt * 16 + fk) * 2;
            const char* ph = smem + SM_AHI + r * AROW_BYTES + kb;
            const char* pl = smem + SM_ALO + r * AROW_BYTES + kb;
            ahi[m][0] = *(const uint32_t*)ph;
            ahi[m][1] = *(const uint32_t*)(ph + 8 * AROW_BYTES);
            ahi[m][2] = *(const uint32_t*)(ph + 16);
            ahi[m][3] = *(const uint32_t*)(ph + 8 * AROW_BYTES + 16);
            alo[m][0] = *(const uint32_t*)pl;
            alo[m][1] = *(const uint32_t*)(pl + 8 * AROW_BYTES);
            alo[m][2] = *(const uint32_t*)(pl + 16);
            alo[m][3] = *(const uint32_t*)(pl + 8 * AROW_BYTES + 16);
        }
#pragma unroll
        for (int nt = 0; nt < 3; nt++) {
            const int g = wn * 3 + nt;
            const int np = g / 6, n6 = g % 6;
            const uint2 bhi = Bfrag[(((0 * 2 + np) * 6 + kt) * 6 + n6) * 32 + lane];
            const uint2 blo = Bfrag[(((1 * 2 + np) * 6 + kt) * 6 + n6) * 32 + lane];
#pragma unroll
            for (int m = 0; m < 2; m++) {
                mma_bf16(acc[m][nt], ahi[m], bhi.x, bhi.y);
                mma_bf16(acc[m][nt], ahi[m], blo.x, blo.y);
                mma_bf16(acc[m][nt], alo[m], bhi.x, bhi.y);
            }
        }
    }

#pragma unroll
    for (int m = 0; m < 2; m++) {
        const int r = row0 + wm * 32 + m * 16 + fr;
        const float d0 = (r < NNODES) ? g_dis[r] : 0.0f;
        const float d1 = (r + 8 < NNODES) ? g_dis[r + 8] : 0.0f;
#pragma unroll
        for (int nt = 0; nt < 3; nt++) {
            const int col = (wn * 3 + nt) * 8 + fk;
            if (r < NNODES)
                *(__half2*)(H + (size_t)r * DH + col) =
                    __floats2half2_rn(acc[m][nt][0] * d0, acc[m][nt][1] * d0);
            if (r + 8 < NNODES)
                *(__half2*)(H + (size_t)(r + 8) * DH + col) =
                    __floats2half2_rn(acc[m][nt][2] * d1, acc[m][nt][3] * d1);
        }
    }
}

// layer-1 GEMM: A staged from input x BEFORE the PDL sync (legal overlap)
__global__ void __launch_bounds__(256)
gemm_f32_kernel(const float* __restrict__ A, const uint2* __restrict__ Bfrag,
                __half* __restrict__ H) {
    extern __shared__ char smem[];
    const int tid = threadIdx.x;
    const int row0 = blockIdx.x * GBM;
    {
        const int r = tid >> 2;
        const int cb = (tid & 3) * 24;
        const int grow = row0 + r;
        char* phi = smem + SM_AHI + r * AROW_BYTES;
        char* plo = smem + SM_ALO + r * AROW_BYTES;
#pragma unroll
        for (int q = 0; q < 6; q++) {
            const int k0 = cb + q * 4;
            float4 v = (grow < NNODES)
                ? *(const float4*)(A + (size_t)grow * DH + k0)
                : make_float4(0.f, 0.f, 0.f, 0.f);
            split_store(phi, plo, k0 * 2, v.x, v.y, v.z, v.w);
        }
    }
    PDL_SYNC();          // need Bfrag (wprep) + dis (scan), transitively done
    __syncthreads();
    gemm_compute(smem, row0, Bfrag, H);
    PDL_TRIGGER();
}

// layer-2 GEMM: A = fp16 activations from gather1 (must sync first)
__global__ void __launch_bounds__(256)
gemm_f16_kernel(const __half* __restrict__ A, const uint2* __restrict__ Bfrag,
                __half* __restrict__ H) {
    extern __shared__ char smem[];
    PDL_SYNC();
    const int tid = threadIdx.x;
    const int row0 = blockIdx.x * GBM;
    {
        const int r = tid >> 2;
        const int cb = (tid & 3) * 24;
        const int grow = row0 + r;
        char* phi = smem + SM_AHI + r * AROW_BYTES;
        char* plo = smem + SM_ALO + r * AROW_BYTES;
#pragma unroll
        for (int q = 0; q < 6; q++) {
            const int k0 = cb + q * 4;
            float4 v = make_float4(0.f, 0.f, 0.f, 0.f);
            if (grow < NNODES) {
                uint2 u = *(const uint2*)(A + (size_t)grow * DH + k0);
                float2 f0 = __half22float2(*reinterpret_cast<__half2*>(&u.x));
                float2 f1 = __half22float2(*reinterpret_cast<__half2*>(&u.y));
                v = make_float4(f0.x, f0.y, f1.x, f1.y);
            }
            split_store(phi, plo, k0 * 2, v.x, v.y, v.z, v.w);
        }
    }
    __syncthreads();
    gemm_compute(smem, row0, Bfrag, H);
    PDL_TRIGGER();
}

// ============================ gather ============================

__device__ __forceinline__ void gather_node(int node, int lid,
                                            const __half* __restrict__ Hin,
                                            const float* __restrict__ bias,
                                            __half* __restrict__ out16,
                                            float* __restrict__ out32) {
    const bool active = lid < C4;
    float4 acc = make_float4(0.f, 0.f, 0.f, 0.f);
    if (active) {
        uint2 u = __ldg((const uint2*)(Hin + (size_t)node * DH) + lid);
        float2 f0 = __half22float2(*reinterpret_cast<__half2*>(&u.x));
        float2 f1 = __half22float2(*reinterpret_cast<__half2*>(&u.y));
        acc = make_float4(f0.x, f0.y, f1.x, f1.y);
    }
    int start = g_off[node] + g_bsum[node >> 9];
    int deg   = g_meta[node];
#pragma unroll 4
    for (int i = 0; i < deg; i++) {
        int s = __ldg(&g_csr[start + i]);
        if (active) {
            uint2 u = __ldg((const uint2*)(Hin + (size_t)s * DH) + lid);
            float2 f0 = __half22float2(*reinterpret_cast<__half2*>(&u.x));
            float2 f1 = __half22float2(*reinterpret_cast<__half2*>(&u.y));
            acc.x += f0.x; acc.y += f0.y; acc.z += f1.x; acc.w += f1.y;
        }
    }
    if (active) {
        float dd = g_dis[node];
        float4 b = __ldg((const float4*)bias + lid);
        acc.x = fmaxf(acc.x * dd + b.x, 0.0f);
        acc.y = fmaxf(acc.y * dd + b.y, 0.0f);
        acc.z = fmaxf(acc.z * dd + b.z, 0.0f);
        acc.w = fmaxf(acc.w * dd + b.w, 0.0f);
        if (out16) {
            uint2 u;
            *reinterpret_cast<__half2*>(&u.x) = __floats2half2_rn(acc.x, acc.y);
            *reinterpret_cast<__half2*>(&u.y) = __floats2half2_rn(acc.z, acc.w);
            ((uint2*)(out16 + (size_t)node * DH))[lid] = u;
        } else {
            ((float4*)(out32 + (size_t)node * DH))[lid] = acc;
        }
    }
}

__global__ void __launch_bounds__(256)
gather_kernel(const __half* __restrict__ Hin, const float* __restrict__ bias,
              __half* __restrict__ out16, float* __restrict__ out32) {
    PDL_SYNC();
    int node = (blockIdx.x * blockDim.x + threadIdx.x) >> 5;
    int lid = threadIdx.x & 31;
    if (node < NNODES)
        gather_node(node, lid, Hin, bias, out16, out32);
    PDL_TRIGGER();
}

// ============================ launch ============================

template <typename... Args>
static void launch_pdl(void (*kern)(Args...), int grid, int block, size_t smem,
                       Args... args) {
    cudaLaunchConfig_t cfg = {};
    cfg.gridDim = dim3(grid);
    cfg.blockDim = dim3(block);
    cfg.dynamicSmemBytes = smem;
    cfg.stream = 0;
    cudaLaunchAttribute attr[1];
    attr[0].id = cudaLaunchAttributeProgrammaticStreamSerialization;
    attr[0].val.programmaticStreamSerializationAllowed = 1;
    cfg.attrs = attr;
    cfg.numAttrs = 1;
    cudaLaunchKernelEx(&cfg, kern, args...);
}

extern "C" void kernel_launch(void* const* d_in, const int* in_sizes, int n_in,
                              void* d_out, int out_size) {
    const float* x  = (const float*)d_in[0];
    const int*   ei = (const int*)d_in[1];
    const float* W1 = (const float*)d_in[2];
    const float* b1 = (const float*)d_in[3];
    const float* W2 = (const float*)d_in[4];
    const float* b2 = (const float*)d_in[5];
    float* out = (float*)d_out;

    void *pH_v, *pAGG_v, *pBf_v;
    cudaGetSymbolAddress(&pH_v, g_H);
    cudaGetSymbolAddress(&pAGG_v, g_AGG);
    cudaGetSymbolAddress(&pBf_v, g_Bfrag);
    __half* pH   = (__half*)pH_v;
    __half* pAGG = (__half*)pAGG_v;
    const uint2* pBf = (const uint2*)pBf_v;

    const int T = 256;
    int nBlkZero = (NNODES + 1 + T - 1) / T;
    int nBlkGath = (NNODES * 32 + T - 1) / T;

    // 1. zero meta (plain launch; head of PDL chain)
    zero_kernel<<<nBlkZero, T>>>();
    // 2. hist (+ per-edge slot) || wprep
    launch_pdl(hist_wprep_kernel, WPREP_BLOCKS + HIST_BLOCKS, T, 0, ei, W1, W2);
    // 3. combined scan (+ dis)
    launch_pdl(scan_kernel, NSBLK, SCHUNK, 0);
    // 4. CSR fill (atomic-free)
    launch_pdl(fill_kernel, HIST_BLOCKS, T, 0, ei);
    // 5. layer-1 GEMM (A-stage overlaps fill via pre-sync staging)
    launch_pdl(gemm_f32_kernel, GEMM_BLOCKS, T, (size_t)GEMM_SMEM,
               (const float*)x, pBf, pH);
    // 6. gather layer 1 -> AGG (fp16 activation, bias+relu fused)
    launch_pdl(gather_kernel, nBlkGath, T, 0,
               (const __half*)pH, b1, pAGG, (float*)nullptr);
    // 7. layer-2 GEMM (fp16 A)
    launch_pdl(gemm_f16_kernel, GEMM_BLOCKS, T, (size_t)GEMM_SMEM,
               (const __half*)pAGG, pBf + 4608, pH);
    // 8. gather layer 2 -> out (fp32)
    launch_pdl(gather_kernel, nBlkGath, T, 0,
               (const __half*)pH, b2, (__half*)nullptr, out);
}

// round 17
// speedup vs baseline: 1.4023x; 1.0433x over previous
#include <cuda_runtime.h>
#include <cuda_bf16.h>
#include <cuda_fp16.h>
#include <cstdint>

#define NNODES 100000
#define NEDGES 800000
#define DH 96
#define C4 (DH / 4)

#define GBM 64
#define GEMM_BLOCKS ((NNODES + GBM - 1) / GBM)   // 1563
#define HIST_BLOCKS ((NEDGES + 255) / 256)       // 3125
#define WPREP_TOTAL (2 * 2 * 2 * 6 * 6 * 32)     // 9216
#define WPREP_BLOCKS ((WPREP_TOTAL + 255) / 256) // 36

// ---- scratch ----
__device__ __half g_H[NNODES * DH];     // Hs table (fp16): dis[r] * (A'@W)[r]
__device__ __half g_AGG[NNODES * DH];   // layer-1 activation (fp16): relu(agg+b1)
__device__ float  g_dis[NNODES];
__device__ int    g_meta[NNODES + 1];   // [0,N)=cnt/deg, [N]=scan ticket
__device__ int    g_epos[NEDGES];       // per-edge slot within its dst bucket
__device__ int    g_off[NNODES];        // per-chunk exclusive prefix
__device__ int    g_bsum[256];          // chunk sums -> exclusive after finalize
__device__ int    g_csr[NEDGES];
// B fragments: [layer][var(hi/lo)][np(2)][kt(6)][nt(6)][lane(32)] -> uint2
__device__ uint2  g_Bfrag[2 * 2 * 2 * 6 * 6 * 32];

#define PDL_SYNC()    cudaGridDependencySynchronize()
#define PDL_TRIGGER() cudaTriggerProgrammaticLaunchCompletion()

// ============================ helpers ============================

__device__ __forceinline__ uint32_t cvt_bf16x2(float lo, float hi) {
    uint32_t r;
    asm("cvt.rn.satfinite.bf16x2.f32 %0, %1, %2;" : "=r"(r) : "f"(hi), "f"(lo));
    return r;
}

__device__ __forceinline__ void mma_bf16(float* c, const uint32_t* a,
                                         uint32_t b0, uint32_t b1) {
    asm volatile(
        "mma.sync.aligned.m16n8k16.row.col.f32.bf16.bf16.f32 "
        "{%0,%1,%2,%3}, {%4,%5,%6,%7}, {%8,%9}, {%0,%1,%2,%3};"
        : "+f"(c[0]), "+f"(c[1]), "+f"(c[2]), "+f"(c[3])
        : "r"(a[0]), "r"(a[1]), "r"(a[2]), "r"(a[3]), "r"(b0), "r"(b1));
}

__device__ __forceinline__ void split_store(char* phi, char* plo, int byte_off,
                                            float x, float y, float z, float w) {
    uint32_t h01 = cvt_bf16x2(x, y);
    uint32_t h23 = cvt_bf16x2(z, w);
    float lx = x - __uint_as_float(h01 << 16);
    float ly = y - __uint_as_float(h01 & 0xFFFF0000u);
    float lz = z - __uint_as_float(h23 << 16);
    float lw = w - __uint_as_float(h23 & 0xFFFF0000u);
    *(uint2*)(phi + byte_off) = make_uint2(h01, h23);
    *(uint2*)(plo + byte_off) = make_uint2(cvt_bf16x2(lx, ly), cvt_bf16x2(lz, lw));
}

// ============================ pre-pass kernels ============================

__global__ void zero_kernel() {
    int i = blockIdx.x * blockDim.x + threadIdx.x;
    if (i < NNODES + 1) g_meta[i] = 0;
}

__device__ __forceinline__ void wprep_body(int idx, const float* __restrict__ W1,
                                           const float* __restrict__ W2) {
    if (idx >= WPREP_TOTAL) return;
    int lane = idx & 31;
    int t = idx >> 5;
    int nt = t % 6;  t /= 6;
    int kt = t % 6;  t /= 6;
    int np = t % 2;  t /= 2;
    int var = t % 2; t /= 2;
    int layer = t;
    const float* W = layer ? W2 : W1;

    int n  = np * 48 + nt * 8 + (lane >> 2);
    int k0 = kt * 16 + (lane & 3) * 2;
    float v[4];
#pragma unroll
    for (int i = 0; i < 4; i++) {
        int k = k0 + (i & 1) + (i >> 1) * 8;
        float w = W[k * DH + n];
        float hi = __bfloat162float(__float2bfloat16(w));
        v[i] = var ? (w - hi) : hi;
    }
    g_Bfrag[idx] = make_uint2(cvt_bf16x2(v[0], v[1]), cvt_bf16x2(v[2], v[3]));
}

// hist (records per-edge slot in g_epos) || wprep
__global__ void hist_wprep_kernel(const int* __restrict__ ei,
                                  const float* __restrict__ W1,
                                  const float* __restrict__ W2) {
    if (blockIdx.x < WPREP_BLOCKS) {
        wprep_body(blockIdx.x * blockDim.x + threadIdx.x, W1, W2);   // inputs only
    } else {
        int e = (blockIdx.x - WPREP_BLOCKS) * blockDim.x + threadIdx.x;
        int d = (e < NEDGES) ? ei[NEDGES + e] : 0;   // input load pre-sync
        PDL_SYNC();                                   // g_meta zeroed
        if (e < NEDGES)
            g_epos[e] = atomicAdd(&g_meta[d], 1);     // count AND slot
    }
    PDL_TRIGGER();
}

// ============================ combined scan ============================

#define SCHUNK 512
#define NSBLK ((NNODES + SCHUNK - 1) / SCHUNK)   // 196

__global__ void scan_kernel() {
    __shared__ int wsum[16];
    __shared__ int s_last;
    PDL_SYNC();
    const int t = threadIdx.x;
    const int lane = t & 31, warp = t >> 5;
    const int i = blockIdx.x * SCHUNK + t;
    const int v = (i < NNODES) ? g_meta[i] : 0;
    int x = v;
#pragma unroll
    for (int o = 1; o < 32; o <<= 1) {
        int y = __shfl_up_sync(0xFFFFFFFF, x, o);
        if (lane >= o) x += y;
    }
    if (lane == 31) wsum[warp] = x;
    __syncthreads();
    if (warp == 0) {
        int s = (lane < 16) ? wsum[lane] : 0;
#pragma unroll
        for (int o = 1; o < 16; o <<= 1) {
            int y = __shfl_up_sync(0xFFFFFFFF, s, o);
            if (lane >= o) s += y;
        }
        if (lane < 16) wsum[lane] = s;
    }
    __syncthreads();
    const int base = (warp > 0) ? wsum[warp - 1] : 0;
    if (i < NNODES) {
        g_off[i] = base + x - v;
        g_dis[i] = rsqrtf((float)v + 1.0f);
    }
    if (t == SCHUNK - 1) g_bsum[blockIdx.x] = base + x;

    // release bsum, take a ticket; the LAST block finalizes (old scan2)
    __threadfence();
    if (t == 0) {
        int ticket = atomicAdd(&g_meta[NNODES], 1);
        s_last = (ticket == NSBLK - 1) ? 1 : 0;
    }
    __syncthreads();
    if (s_last && warp == 0) {
        const int b7 = lane * 7;
        int vv[7], inc[7];
        int tot = 0;
#pragma unroll
        for (int j = 0; j < 7; j++) {
            vv[j] = (b7 + j < NSBLK) ? __ldcg(&g_bsum[b7 + j]) : 0;
            tot += vv[j];
            inc[j] = tot;
        }
        int xx = tot;
#pragma unroll
        for (int o = 1; o < 32; o <<= 1) {
            int y = __shfl_up_sync(0xFFFFFFFF, xx, o);
            if (lane >= o) xx += y;
        }
        const int excl = xx - tot;
#pragma unroll
        for (int j = 0; j < 7; j++)
            if (b7 + j < NSBLK) g_bsum[b7 + j] = excl + inc[j] - vv[j];
    }
    PDL_TRIGGER();
}

// ============================ fill (early trigger) ============================
// PDL_TRIGGER fires right after the sync: scan is fully complete+visible at
// that point, so the next kernel (gemm1, which reads only scan/wprep outputs)
// launches and runs CONCURRENTLY with the scatter body. gather1's own
// grid-dependency sync still waits for fill's full completion before
// touching g_csr.

__global__ void fill_kernel(const int* __restrict__ ei) {
    int e = blockIdx.x * blockDim.x + threadIdx.x;
    int s = 0, d = 0;
    if (e < NEDGES) { s = ei[e]; d = ei[NEDGES + e]; }   // input loads pre-sync
    PDL_SYNC();
    PDL_TRIGGER();          // release gemm1 NOW (it doesn't read g_csr)
    if (e < NEDGES) {
        int pos = g_off[d] + g_bsum[d >> 9] + g_epos[e];
        g_csr[pos] = s;
    }
}

// ============================ GEMM (HMMA) ============================

#define APITCH 104
#define AROW_BYTES (APITCH * 2)
#define SM_AHI 0
#define SM_ALO (GBM * AROW_BYTES)
#define GEMM_SMEM (2 * GBM * AROW_BYTES)   // 26624

__device__ __forceinline__ void gemm_compute(char* smem, int row0,
                                             const uint2* __restrict__ Bfrag,
                                             __half* __restrict__ H) {
    const int tid = threadIdx.x;
    const int lane = tid & 31;
    const int wid = tid >> 5;
    const int wm = wid & 1;
    const int wn = wid >> 1;

    float acc[2][3][4];
#pragma unroll
    for (int m = 0; m < 2; m++)
#pragma unroll
        for (int nt = 0; nt < 3; nt++)
#pragma unroll
            for (int i = 0; i < 4; i++) acc[m][nt][i] = 0.0f;

    const int fr = (lane >> 2);
    const int fk = (lane & 3) * 2;

#pragma unroll
    for (int kt = 0; kt < 6; kt++) {
        uint32_t ahi[2][4], alo[2][4];
#pragma unroll
        for (int m = 0; m < 2; m++) {
            const int r = wm * 32 + m * 16 + fr;
            const int kb = (kt * 16 + fk) * 2;
            const char* ph = smem + SM_AHI + r * AROW_BYTES + kb;
            const char* pl = smem + SM_ALO + r * AROW_BYTES + kb;
            ahi[m][0] = *(const uint32_t*)ph;
            ahi[m][1] = *(const uint32_t*)(ph + 8 * AROW_BYTES);
            ahi[m][2] = *(const uint32_t*)(ph + 16);
            ahi[m][3] = *(const uint32_t*)(ph + 8 * AROW_BYTES + 16);
            alo[m][0] = *(const uint32_t*)pl;
            alo[m][1] = *(const uint32_t*)(pl + 8 * AROW_BYTES);
            alo[m][2] = *(const uint32_t*)(pl + 16);
            alo[m][3] = *(const uint32_t*)(pl + 8 * AROW_BYTES + 16);
        }
#pragma unroll
        for (int nt = 0; nt < 3; nt++) {
            const int g = wn * 3 + nt;
            const int np = g / 6, n6 = g % 6;
            const uint2 bhi = Bfrag[(((0 * 2 + np) * 6 + kt) * 6 + n6) * 32 + lane];
            const uint2 blo = Bfrag[(((1 * 2 + np) * 6 + kt) * 6 + n6) * 32 + lane];
#pragma unroll
            for (int m = 0; m < 2; m++) {
                mma_bf16(acc[m][nt], ahi[m], bhi.x, bhi.y);
                mma_bf16(acc[m][nt], ahi[m], blo.x, blo.y);
                mma_bf16(acc[m][nt], alo[m], bhi.x, bhi.y);
            }
        }
    }

#pragma unroll
    for (int m = 0; m < 2; m++) {
        const int r = row0 + wm * 32 + m * 16 + fr;
        const float d0 = (r < NNODES) ? g_dis[r] : 0.0f;
        const float d1 = (r + 8 < NNODES) ? g_dis[r + 8] : 0.0f;
#pragma unroll
        for (int nt = 0; nt < 3; nt++) {
            const int col = (wn * 3 + nt) * 8 + fk;
            if (r < NNODES)
                *(__half2*)(H + (size_t)r * DH + col) =
                    __floats2half2_rn(acc[m][nt][0] * d0, acc[m][nt][1] * d0);
            if (r + 8 < NNODES)
                *(__half2*)(H + (size_t)(r + 8) * DH + col) =
                    __floats2half2_rn(acc[m][nt][2] * d1, acc[m][nt][3] * d1);
        }
    }
}

// layer-1 GEMM: NO grid-dependency sync. It launches only after fill's
// trigger, which fires after fill's sync returned => scan & wprep grids are
// fully complete and visible. gemm1 reads x (input), Bfrag (wprep), dis
// (scan) — never g_csr — so it legally overlaps fill's scatter body.
__global__ void __launch_bounds__(256)
gemm_f32_kernel(const float* __restrict__ A, const uint2* __restrict__ Bfrag,
                __half* __restrict__ H) {
    extern __shared__ char smem[];
    const int tid = threadIdx.x;
    const int row0 = blockIdx.x * GBM;
    {
        const int r = tid >> 2;
        const int cb = (tid & 3) * 24;
        const int grow = row0 + r;
        char* phi = smem + SM_AHI + r * AROW_BYTES;
        char* plo = smem + SM_ALO + r * AROW_BYTES;
#pragma unroll
        for (int q = 0; q < 6; q++) {
            const int k0 = cb + q * 4;
            float4 v = (grow < NNODES)
                ? *(const float4*)(A + (size_t)grow * DH + k0)
                : make_float4(0.f, 0.f, 0.f, 0.f);
            split_store(phi, plo, k0 * 2, v.x, v.y, v.z, v.w);
        }
    }
    __syncthreads();
    gemm_compute(smem, row0, Bfrag, H);
    PDL_TRIGGER();
}

// layer-2 GEMM: A = fp16 activations from gather1 (must sync first)
__global__ void __launch_bounds__(256)
gemm_f16_kernel(const __half* __restrict__ A, const uint2* __restrict__ Bfrag,
                __half* __restrict__ H) {
    extern __shared__ char smem[];
    PDL_SYNC();
    const int tid = threadIdx.x;
    const int row0 = blockIdx.x * GBM;
    {
        const int r = tid >> 2;
        const int cb = (tid & 3) * 24;
        const int grow = row0 + r;
        char* phi = smem + SM_AHI + r * AROW_BYTES;
        char* plo = smem + SM_ALO + r * AROW_BYTES;
#pragma unroll
        for (int q = 0; q < 6; q++) {
            const int k0 = cb + q * 4;
            float4 v = make_float4(0.f, 0.f, 0.f, 0.f);
            if (grow < NNODES) {
                uint2 u = *(const uint2*)(A + (size_t)grow * DH + k0);
                float2 f0 = __half22float2(*reinterpret_cast<__half2*>(&u.x));
                float2 f1 = __half22float2(*reinterpret_cast<__half2*>(&u.y));
                v = make_float4(f0.x, f0.y, f1.x, f1.y);
            }
            split_store(phi, plo, k0 * 2, v.x, v.y, v.z, v.w);
        }
    }
    __syncthreads();
    gemm_compute(smem, row0, Bfrag, H);
    PDL_TRIGGER();
}

// ============================ gather ============================
// Pre-sync: node metadata (off/bsum/deg/dis) and bias — all produced >=2
// grids upstream, complete before this kernel can launch. Post-sync: csr + H.

__global__ void __launch_bounds__(256)
gather_kernel(const __half* __restrict__ Hin, const float* __restrict__ bias,
              __half* __restrict__ out16, float* __restrict__ out32) {
    int node = (blockIdx.x * blockDim.x + threadIdx.x) >> 5;
    int lid = threadIdx.x & 31;
    const bool valid = node < NNODES;
    const bool active = valid && (lid < C4);

    int start = 0, deg = 0;
    float dd = 0.0f;
    float4 b = make_float4(0.f, 0.f, 0.f, 0.f);
    if (valid) {
        start = g_off[node] + g_bsum[node >> 9];
        deg   = g_meta[node];
        dd    = g_dis[node];
    }
    if (active) b = __ldg((const float4*)bias + lid);

    PDL_SYNC();

    float4 acc = make_float4(0.f, 0.f, 0.f, 0.f);
    if (active) {
        uint2 u = __ldg((const uint2*)(Hin + (size_t)node * DH) + lid);
        float2 f0 = __half22float2(*reinterpret_cast<__half2*>(&u.x));
        float2 f1 = __half22float2(*reinterpret_cast<__half2*>(&u.y));
        acc = make_float4(f0.x, f0.y, f1.x, f1.y);
    }
#pragma unroll 4
    for (int i = 0; i < deg; i++) {
        int s = __ldg(&g_csr[start + i]);
        if (active) {
            uint2 u = __ldg((const uint2*)(Hin + (size_t)s * DH) + lid);
            float2 f0 = __half22float2(*reinterpret_cast<__half2*>(&u.x));
            float2 f1 = __half22float2(*reinterpret_cast<__half2*>(&u.y));
            acc.x += f0.x; acc.y += f0.y; acc.z += f1.x; acc.w += f1.y;
        }
    }
    if (active) {
        acc.x = fmaxf(acc.x * dd + b.x, 0.0f);
        acc.y = fmaxf(acc.y * dd + b.y, 0.0f);
        acc.z = fmaxf(acc.z * dd + b.z, 0.0f);
        acc.w = fmaxf(acc.w * dd + b.w, 0.0f);
        if (out16) {
            uint2 u;
            *reinterpret_cast<__half2*>(&u.x) = __floats2half2_rn(acc.x, acc.y);
            *reinterpret_cast<__half2*>(&u.y) = __floats2half2_rn(acc.z, acc.w);
            ((uint2*)(out16 + (size_t)node * DH))[lid] = u;
        } else {
            ((float4*)(out32 + (size_t)node * DH))[lid] = acc;
        }
    }
    PDL_TRIGGER();
}

// ============================ launch ============================

template <typename... Args>
static void launch_pdl(void (*kern)(Args...), int grid, int block, size_t smem,
                       Args... args) {
    cudaLaunchConfig_t cfg = {};
    cfg.gridDim = dim3(grid);
    cfg.blockDim = dim3(block);
    cfg.dynamicSmemBytes = smem;
    cfg.stream = 0;
    cudaLaunchAttribute attr[1];
    attr[0].id = cudaLaunchAttributeProgrammaticStreamSerialization;
    attr[0].val.programmaticStreamSerializationAllowed = 1;
    cfg.attrs = attr;
    cfg.numAttrs = 1;
    cudaLaunchKernelEx(&cfg, kern, args...);
}

extern "C" void kernel_launch(void* const* d_in, const int* in_sizes, int n_in,
                              void* d_out, int out_size) {
    const float* x  = (const float*)d_in[0];
    const int*   ei = (const int*)d_in[1];
    const float* W1 = (const float*)d_in[2];
    const float* b1 = (const float*)d_in[3];
    const float* W2 = (const float*)d_in[4];
    const float* b2 = (const float*)d_in[5];
    float* out = (float*)d_out;

    void *pH_v, *pAGG_v, *pBf_v;
    cudaGetSymbolAddress(&pH_v, g_H);
    cudaGetSymbolAddress(&pAGG_v, g_AGG);
    cudaGetSymbolAddress(&pBf_v, g_Bfrag);
    __half* pH   = (__half*)pH_v;
    __half* pAGG = (__half*)pAGG_v;
    const uint2* pBf = (const uint2*)pBf_v;

    const int T = 256;
    int nBlkZero = (NNODES + 1 + T - 1) / T;
    int nBlkGath = (NNODES * 32 + T - 1) / T;

    // 1. zero meta (head of PDL chain)
    zero_kernel<<<nBlkZero, T>>>();
    // 2. hist (+ per-edge slot) || wprep
    launch_pdl(hist_wprep_kernel, WPREP_BLOCKS + HIST_BLOCKS, T, 0, ei, W1, W2);
    // 3. combined scan (+ dis)
    launch_pdl(scan_kernel, NSBLK, SCHUNK, 0);
    // 4. CSR fill — early trigger: releases gemm1 before the scatter body
    launch_pdl(fill_kernel, HIST_BLOCKS, T, 0, ei);
    // 5. layer-1 GEMM — no sync; overlaps fill's scatter
    launch_pdl(gemm_f32_kernel, GEMM_BLOCKS, T, (size_t)GEMM_SMEM,
               (const float*)x, pBf, pH);
    // 6. gather layer 1 -> AGG (fp16 activation, bias+relu fused)
    launch_pdl(gather_kernel, nBlkGath, T, 0,
               (const __half*)pH, b1, pAGG, (float*)nullptr);
    // 7. layer-2 GEMM (fp16 A)
    launch_pdl(gemm_f16_kernel, GEMM_BLOCKS, T, (size_t)GEMM_SMEM,
               (const __half*)pAGG, pBf + 4608, pH);
    // 8. gather layer 2 -> out (fp32)
    launch_pdl(gather_kernel, nBlkGath, T, 0,
               (const __half*)pH, b2, (__half*)nullptr, out);
}